// round 2
// baseline (speedup 1.0000x reference)
#include <cuda_runtime.h>
#include <math.h>

#define NP 160000
#define NN 10000
#define FD 32
#define NH 7
#define NC 224
#define NRBF 50

// ---------------- scratch (device globals: allocation-free) ----------------
__device__ float g_hedge[FD * NP];          // column-major [f][p]
__device__ float g_logits[NP * NH];
__device__ float g_att[NP * NH];
__device__ float g_dir[NP * 3];
__device__ float g_xmix[NP * NC];           // 143 MB
__device__ int   g_counts[NN];
__device__ int   g_cursor[NN];
__device__ int   g_offsets[NN + 1];
__device__ int   g_order[NP];

// ---------------- constant memory for edge-model weights ------
__constant__ float c_wmlp[64 * NRBF];
__constant__ float c_bmlp[NRBF];
__constant__ float c_we1[115 * FD];
__constant__ float c_be1[FD];
__constant__ float c_we2[FD * FD];
__constant__ float c_be2[FD];
__constant__ float c_watt[FD * NH];
__constant__ float c_batt[NH];

__device__ __forceinline__ float siluf(float z) { return z / (1.0f + __expf(-z)); }

__device__ __forceinline__ void fma2(unsigned long long& acc, unsigned long long a, unsigned long long b) {
    asm("fma.rn.f32x2 %0, %1, %2, %0;" : "+l"(acc) : "l"(a), "l"(b));
}
__device__ __forceinline__ float2 unpack2(unsigned long long v) {
    float2 f; asm("mov.b64 {%0,%1}, %2;" : "=f"(f.x), "=f"(f.y) : "l"(v)); return f;
}

// ---------------- CSR build ----------------
__global__ void zero_kernel() {
    int i = blockIdx.x * 256 + threadIdx.x;
    if (i < NN) { g_counts[i] = 0; g_cursor[i] = 0; }
}

__global__ void count_kernel(const int* __restrict__ pl) {
    int p = blockIdx.x * 256 + threadIdx.x;
    if (p < NP) atomicAdd(&g_counts[pl[p]], 1);
}

__global__ void scan_kernel() {
    __shared__ int sh[1024];
    int t = threadIdx.x;
    int carry = 0;
    if (t == 0) g_offsets[0] = 0;
    for (int base = 0; base < NN; base += 1024) {
        int idx = base + t;
        int val = (idx < NN) ? g_counts[idx] : 0;
        sh[t] = val;
        __syncthreads();
        for (int off = 1; off < 1024; off <<= 1) {
            int add = (t >= off) ? sh[t - off] : 0;
            __syncthreads();
            sh[t] += add;
            __syncthreads();
        }
        if (idx < NN) g_offsets[idx + 1] = carry + sh[t];
        int tot = sh[1023];
        __syncthreads();
        carry += tot;
    }
}

__global__ void scatter_kernel(const int* __restrict__ pl) {
    int p = blockIdx.x * 256 + threadIdx.x;
    if (p < NP) {
        int i = pl[p];
        int pos = g_offsets[i] + atomicAdd(&g_cursor[i], 1);
        g_order[pos] = p;
    }
}

// ---------------- edge model ----------------
__global__ void __launch_bounds__(128) edge_kernel(
    const float* __restrict__ h, const float* __restrict__ x,
    const int* __restrict__ pl)
{
    extern __shared__ float smem[];
    float* my = smem + threadIdx.x * 121;
    int p = blockIdx.x * 128 + threadIdx.x;   // grid exactly covers NP

    int i = pl[p], j = pl[NP + p];
    float xi0 = x[i*3], xi1 = x[i*3+1], xi2 = x[i*3+2];
    float r0 = x[j*3] - xi0, r1 = x[j*3+1] - xi1, r2 = x[j*3+2] - xi2;
    float d = sqrtf(r0*r0 + r1*r1 + r2*r2);
    float inv = 1.0f / (d + 1e-5f);
    g_dir[p*3]   = r0 * inv;
    g_dir[p*3+1] = r1 * inv;
    g_dir[p*3+2] = r2 * inv;

    // h_cat into scratch[0..63]
    const float4* hi = (const float4*)(h + i * FD);
    const float4* hj = (const float4*)(h + j * FD);
    #pragma unroll
    for (int q = 0; q < 8; q++) {
        float4 a = hi[q];
        my[4*q] = a.x; my[4*q+1] = a.y; my[4*q+2] = a.z; my[4*q+3] = a.w;
    }
    #pragma unroll
    for (int q = 0; q < 8; q++) {
        float4 a = hj[q];
        my[32+4*q] = a.x; my[32+4*q+1] = a.y; my[32+4*q+2] = a.z; my[32+4*q+3] = a.w;
    }

    // stage 1: t[50] = h_cat @ w_mlp_in + b
    float acc[NRBF];
    #pragma unroll
    for (int k = 0; k < NRBF; k++) acc[k] = c_bmlp[k];
    #pragma unroll 2
    for (int c = 0; c < 64; c++) {
        float v = my[c];
        #pragma unroll
        for (int k = 0; k < NRBF; k++) acc[k] += v * c_wmlp[c * NRBF + k];
    }
    // filt = rbf(d) * t -> scratch[64..113], d -> scratch[114]
    #pragma unroll
    for (int k = 0; k < NRBF; k++) {
        float ce = d - (float)k * (5.0f / 49.0f);
        my[64 + k] = __expf(-10.0f * ce * ce) * acc[k];
    }
    my[114] = d;

    // stage 2: u = silu(e_in @ w_e1 + b_e1)
    float a2[FD];
    #pragma unroll
    for (int k = 0; k < FD; k++) a2[k] = c_be1[k];
    #pragma unroll 2
    for (int c = 0; c < 115; c++) {
        float v = my[c];
        #pragma unroll
        for (int k = 0; k < FD; k++) a2[k] += v * c_we1[c * FD + k];
    }
    #pragma unroll
    for (int k = 0; k < FD; k++) my[k] = siluf(a2[k]);   // reuse scratch

    // stage 3: h_edge = u @ w_e2 + b_e2
    float a3[FD];
    #pragma unroll
    for (int k = 0; k < FD; k++) a3[k] = c_be2[k];
    #pragma unroll 2
    for (int c = 0; c < FD; c++) {
        float v = my[c];
        #pragma unroll
        for (int k = 0; k < FD; k++) a3[k] += v * c_we2[c * FD + k];
    }
    #pragma unroll
    for (int k = 0; k < FD; k++) {
        g_hedge[k * NP + p] = a3[k];  // column-major store
        my[k] = a3[k];
    }

    // stage 4: logits = celu(h_edge @ w_att + b_att, alpha=2)
    float a4[NH];
    #pragma unroll
    for (int k = 0; k < NH; k++) a4[k] = c_batt[k];
    #pragma unroll 2
    for (int c = 0; c < FD; c++) {
        float v = my[c];
        #pragma unroll
        for (int k = 0; k < NH; k++) a4[k] += v * c_watt[c * NH + k];
    }
    #pragma unroll
    for (int k = 0; k < NH; k++) {
        float z = a4[k];
        float cel = (z > 0.0f) ? z : 2.0f * (__expf(0.5f * z) - 1.0f);
        g_logits[p * NH + k] = cel;
    }
}

// ---------------- scatter softmax (warp per node, CSR) ----------------
__global__ void __launch_bounds__(256) softmax_kernel() {
    int node = blockIdx.x * 8 + (threadIdx.x >> 5);
    int lane = threadIdx.x & 31;
    int s = g_offsets[node], e = g_offsets[node + 1];

    float mx[NH];
    #pragma unroll
    for (int k = 0; k < NH; k++) mx[k] = -1e30f;
    for (int idx = s + lane; idx < e; idx += 32) {
        int p = g_order[idx];
        #pragma unroll
        for (int k = 0; k < NH; k++) mx[k] = fmaxf(mx[k], g_logits[p * NH + k]);
    }
    #pragma unroll
    for (int k = 0; k < NH; k++)
        #pragma unroll
        for (int off = 16; off; off >>= 1)
            mx[k] = fmaxf(mx[k], __shfl_xor_sync(0xffffffffu, mx[k], off));

    float sm[NH];
    #pragma unroll
    for (int k = 0; k < NH; k++) sm[k] = 0.0f;
    for (int idx = s + lane; idx < e; idx += 32) {
        int p = g_order[idx];
        #pragma unroll
        for (int k = 0; k < NH; k++) sm[k] += __expf(g_logits[p * NH + k] - mx[k]);
    }
    #pragma unroll
    for (int k = 0; k < NH; k++)
        #pragma unroll
        for (int off = 16; off; off >>= 1)
            sm[k] += __shfl_xor_sync(0xffffffffu, sm[k], off);

    for (int idx = s + lane; idx < e; idx += 32) {
        int p = g_order[idx];
        #pragma unroll
        for (int k = 0; k < NH; k++)
            g_att[p * NH + k] = __expf(g_logits[p * NH + k] - mx[k]) / sm[k];
    }
}

// ---------------- big GEMM: x_mixed = tanh(sem @ w_xmix) ----------------
// BM=64 pairs, N=224 full, BK=16. 256 threads, thread tile 8m x 7n.
// Packed fma.rn.f32x2 along m; weight tile stored DUPLICATED (w,w) in smem so
// the b-operand is a single LDS.64 (no packing MOVs).
__global__ void __launch_bounds__(256) gemm_kernel(const float* __restrict__ wx) {
    extern __shared__ float sm[];
    float* semT = sm;              // [224][64]
    float* wdup = sm + NC * 64;    // 7168 floats: 16 x 224 duplicated pairs

    int tid = threadIdx.x;
    int m0 = blockIdx.x * 64;

    // stage h_edge tile [32][64] and att tile [448] into wdup region
    float* s_he = wdup;            // 2048 floats
    float* s_att = wdup + 2048;    // 448 floats
    {
        int m = tid & 63, f0 = tid >> 6;
        #pragma unroll
        for (int it = 0; it < 8; it++) {
            int f = f0 + 4 * it;
            s_he[f * 64 + m] = g_hedge[f * NP + m0 + m];
        }
    }
    for (int t2 = tid; t2 < 448; t2 += 256) s_att[t2] = g_att[m0 * NH + t2];
    __syncthreads();

    // semT[k][m] = he[k/7][m] * att[m][k%7]
    for (int idx = tid; idx < NC * 64; idx += 256) {
        int k = idx >> 6, m = idx & 63;
        semT[idx] = s_he[(k / 7) * 64 + m] * s_att[m * 7 + (k % 7)];
    }

    int tn = tid & 31, tm = tid >> 5;
    unsigned long long r2[4][7];
    #pragma unroll
    for (int j = 0; j < 4; j++)
        #pragma unroll
        for (int q = 0; q < 7; q++) r2[j][q] = 0ull;

    for (int kt = 0; kt < 14; kt++) {
        __syncthreads();   // previous compute (and semT build) done reading wdup
        const float4* src = (const float4*)(wx + kt * 16 * NC);
        float2* dst = (float2*)wdup;
        for (int t4 = tid; t4 < 896; t4 += 256) {
            float4 w = src[t4];
            dst[t4 * 4 + 0] = make_float2(w.x, w.x);
            dst[t4 * 4 + 1] = make_float2(w.y, w.y);
            dst[t4 * 4 + 2] = make_float2(w.z, w.z);
            dst[t4 * 4 + 3] = make_float2(w.w, w.w);
        }
        __syncthreads();

        #pragma unroll
        for (int kk = 0; kk < 16; kk++) {
            int k = kt * 16 + kk;
            const ulonglong2* sa = (const ulonglong2*)(semT + k * 64 + tm * 8);
            ulonglong2 A0 = sa[0], A1 = sa[1];
            unsigned long long a[4] = {A0.x, A0.y, A1.x, A1.y};
            const unsigned long long* bb = ((const unsigned long long*)wdup) + kk * NC;
            #pragma unroll
            for (int q = 0; q < 7; q++) {
                unsigned long long b = bb[tn + 32 * q];
                fma2(r2[0][q], a[0], b);
                fma2(r2[1][q], a[1], b);
                fma2(r2[2][q], a[2], b);
                fma2(r2[3][q], a[3], b);
            }
        }
    }

    #pragma unroll
    for (int j = 0; j < 4; j++) {
        int p = m0 + tm * 8 + 2 * j;
        #pragma unroll
        for (int q = 0; q < 7; q++) {
            float2 rv = unpack2(r2[j][q]);
            g_xmix[p * NC + tn + 32 * q] = tanhf(rv.x);
            g_xmix[(p + 1) * NC + tn + 32 * q] = tanhf(rv.y);
        }
    }
}

// ---------------- per-node aggregation + node/velocity MLPs ----------------
// Weights cached in dynamic smem (LDS beats per-warp LDG streams).
__global__ void __launch_bounds__(256) node_kernel(
    const float* __restrict__ h, const float* __restrict__ x, const float* __restrict__ v,
    const float* __restrict__ w_p1, const float* __restrict__ b_p1,
    const float* __restrict__ w_p2, const float* __restrict__ b_p2,
    const float* __restrict__ w_n1, const float* __restrict__ b_n1,
    const float* __restrict__ w_n2, const float* __restrict__ b_n2,
    const float* __restrict__ w_v1, const float* __restrict__ b_v1,
    const float* __restrict__ w_v2, const float* __restrict__ w_vmix,
    float* __restrict__ out)
{
    extern __shared__ float dsm[];
    float* s_wp1 = dsm;                  // 7168
    float* s_wp2 = s_wp1 + 7168;         // 1024
    float* s_wn1 = s_wp2 + 1024;         // 9216
    float* s_wn2 = s_wn1 + 9216;         // 1024
    float* s_wv1 = s_wn2 + 1024;         // 1024
    float* s_wv2 = s_wv1 + 1024;         // 32
    float* s_wvm = s_wv2 + 32;           // 224
    float* s_ws  = s_wvm + 224;          // 8*512

    int tid = threadIdx.x;
    // cooperative weight load
    for (int t = tid; t < 7168; t += 256) s_wp1[t] = w_p1[t];
    for (int t = tid; t < 1024; t += 256) s_wp2[t] = w_p2[t];
    for (int t = tid; t < 9216; t += 256) s_wn1[t] = w_n1[t];
    for (int t = tid; t < 1024; t += 256) s_wn2[t] = w_n2[t];
    for (int t = tid; t < 1024; t += 256) s_wv1[t] = w_v1[t];
    if (tid < 32) s_wv2[tid] = w_v2[tid];
    for (int t = tid; t < 224; t += 256) s_wvm[t] = w_vmix[t];
    __syncthreads();

    int wid = tid >> 5, lane = tid & 31;
    float* ws = s_ws + wid * 512;   // [0..223] ns, [224..447] hsem, [448..479] he, [480..486] att
    int node = blockIdx.x * 8 + wid;
    int s = g_offsets[node], e = g_offsets[node + 1];

    int fj[7], hj[7];
    #pragma unroll
    for (int j = 0; j < 7; j++) { int c = lane + 32 * j; fj[j] = c / 7; hj[j] = c % 7; }

    float hs[7]  = {0,0,0,0,0,0,0};
    float cb0[7] = {0,0,0,0,0,0,0};
    float cb1[7] = {0,0,0,0,0,0,0};
    float cb2[7] = {0,0,0,0,0,0,0};

    for (int idx = s; idx < e; idx++) {
        int p = g_order[idx];
        ws[448 + lane] = g_hedge[lane * NP + p];
        if (lane < 7) ws[480 + lane] = g_att[p * NH + lane];
        float d0 = g_dir[p*3], d1 = g_dir[p*3+1], d2 = g_dir[p*3+2];
        __syncwarp();
        #pragma unroll
        for (int j = 0; j < 7; j++) {
            int c = lane + 32 * j;
            float xm = g_xmix[p * NC + c];
            hs[j]  += ws[448 + fj[j]] * ws[480 + hj[j]];
            cb0[j] += d0 * xm; cb1[j] += d1 * xm; cb2[j] += d2 * xm;
        }
        __syncwarp();
    }

    float rden = 1.0f / fmaxf((float)(e - s), 1.0f);
    float vp0 = 0, vp1 = 0, vp2 = 0;
    #pragma unroll
    for (int j = 0; j < 7; j++) {
        int c = lane + 32 * j;
        float m0 = cb0[j] * rden, m1 = cb1[j] * rden, m2 = cb2[j] * rden;
        ws[c] = m0*m0 + m1*m1 + m2*m2;   // norm_sq
        ws[224 + c] = hs[j];             // h_i_semantic
        float wv = s_wvm[c];
        vp0 += wv * m0; vp1 += wv * m1; vp2 += wv * m2;
    }
    #pragma unroll
    for (int off = 16; off; off >>= 1) {
        vp0 += __shfl_xor_sync(0xffffffffu, vp0, off);
        vp1 += __shfl_xor_sync(0xffffffffu, vp1, off);
        vp2 += __shfl_xor_sync(0xffffffffu, vp2, off);
    }
    __syncwarp();

    // spatial MLP: silu(silu(ns @ w_p1 + b) @ w_p2 + b)
    float o1 = __ldg(&b_p1[lane]);
    for (int c = 0; c < NC; c++) o1 += ws[c] * s_wp1[c * 32 + lane];
    o1 = siluf(o1);
    float o2 = __ldg(&b_p2[lane]);
    for (int c = 0; c < 32; c++)
        o2 += __shfl_sync(0xffffffffu, o1, c) * s_wp2[c * 32 + lane];
    float hspat = siluf(o2);

    // node MLP
    float hv = h[node * 32 + lane];
    float n1 = __ldg(&b_n1[lane]);
    for (int c = 0; c < 32; c++)
        n1 += __shfl_sync(0xffffffffu, hv, c) * s_wn1[c * 32 + lane];
    for (int c = 0; c < NC; c++)
        n1 += ws[224 + c] * s_wn1[(32 + c) * 32 + lane];
    for (int c = 0; c < 32; c++)
        n1 += __shfl_sync(0xffffffffu, hspat, c) * s_wn1[(256 + c) * 32 + lane];
    n1 = siluf(n1);
    float n2 = __ldg(&b_n2[lane]);
    for (int c = 0; c < 32; c++)
        n2 += __shfl_sync(0xffffffffu, n1, c) * s_wn2[c * 32 + lane];
    float hup = hv + siluf(n2);
    out[node * 32 + lane] = hup;

    // velocity MLP
    float v1 = __ldg(&b_v1[lane]);
    for (int c = 0; c < 32; c++)
        v1 += __shfl_sync(0xffffffffu, hv, c) * s_wv1[c * 32 + lane];
    v1 = siluf(v1);
    float sv = v1 * s_wv2[lane];
    #pragma unroll
    for (int off = 16; off; off >>= 1) sv += __shfl_xor_sync(0xffffffffu, sv, off);
    float scale = 2.0f / (1.0f + __expf(-sv));

    if (lane < 3) {
        float dv = (lane == 0) ? vp0 : ((lane == 1) ? vp1 : vp2);
        float vu = scale * v[node * 3 + lane] + dv;
        out[NN * 32 + node * 3 + lane] = x[node * 3 + lane] + vu;   // x_updated
        out[NN * 32 + NN * 3 + node * 3 + lane] = vu;               // v_updated
    }
}

// ---------------- launch ----------------
extern "C" void kernel_launch(void* const* d_in, const int* in_sizes, int n_in,
                              void* d_out, int out_size)
{
    const float* h  = (const float*)d_in[0];
    const float* x  = (const float*)d_in[1];
    const float* v  = (const float*)d_in[2];
    const int*   pl = (const int*)d_in[3];

    cudaMemcpyToSymbolAsync(c_wmlp, d_in[4], 64 * NRBF * 4, 0, cudaMemcpyDeviceToDevice, 0);
    cudaMemcpyToSymbolAsync(c_bmlp, d_in[5], NRBF * 4,      0, cudaMemcpyDeviceToDevice, 0);
    cudaMemcpyToSymbolAsync(c_we1,  d_in[6], 115 * FD * 4,  0, cudaMemcpyDeviceToDevice, 0);
    cudaMemcpyToSymbolAsync(c_be1,  d_in[7], FD * 4,        0, cudaMemcpyDeviceToDevice, 0);
    cudaMemcpyToSymbolAsync(c_we2,  d_in[8], FD * FD * 4,   0, cudaMemcpyDeviceToDevice, 0);
    cudaMemcpyToSymbolAsync(c_be2,  d_in[9], FD * 4,        0, cudaMemcpyDeviceToDevice, 0);
    cudaMemcpyToSymbolAsync(c_watt, d_in[10], FD * NH * 4,  0, cudaMemcpyDeviceToDevice, 0);
    cudaMemcpyToSymbolAsync(c_batt, d_in[11], NH * 4,       0, cudaMemcpyDeviceToDevice, 0);

    int edge_smem = 128 * 121 * 4;
    int gemm_smem = (NC * 64 + 7168) * 4;       // 86016 B
    int node_smem = (7168 + 1024 + 9216 + 1024 + 1024 + 32 + 224 + 8 * 512) * 4;  // 95232 B
    cudaFuncSetAttribute(edge_kernel, cudaFuncAttributeMaxDynamicSharedMemorySize, edge_smem);
    cudaFuncSetAttribute(gemm_kernel, cudaFuncAttributeMaxDynamicSharedMemorySize, gemm_smem);
    cudaFuncSetAttribute(node_kernel, cudaFuncAttributeMaxDynamicSharedMemorySize, node_smem);

    zero_kernel<<<(NN + 255) / 256, 256>>>();
    count_kernel<<<(NP + 255) / 256, 256>>>(pl);
    scan_kernel<<<1, 1024>>>();
    scatter_kernel<<<(NP + 255) / 256, 256>>>(pl);

    edge_kernel<<<NP / 128, 128, edge_smem>>>(h, x, pl);
    softmax_kernel<<<NN / 8, 256>>>();
    gemm_kernel<<<NP / 64, 256, gemm_smem>>>((const float*)d_in[23]);

    node_kernel<<<NN / 8, 256, node_smem>>>(
        h, x, v,
        (const float*)d_in[16], (const float*)d_in[17],   // w_p1, b_p1
        (const float*)d_in[18], (const float*)d_in[19],   // w_p2, b_p2
        (const float*)d_in[12], (const float*)d_in[13],   // w_n1, b_n1
        (const float*)d_in[14], (const float*)d_in[15],   // w_n2, b_n2
        (const float*)d_in[20], (const float*)d_in[21],   // w_v1, b_v1
        (const float*)d_in[22], (const float*)d_in[24],   // w_v2, w_vmix
        (float*)d_out);
}

// round 3
// speedup vs baseline: 1.3236x; 1.3236x over previous
#include <cuda_runtime.h>
#include <math.h>

#define NP 160000
#define NN 10000
#define FD 32
#define NH 7
#define NC 224
#define NRBF 50

// ---------------- scratch (device globals: allocation-free) ----------------
__device__ float g_hedge[FD * NP];          // column-major [f][p]
__device__ float g_logits[NP * NH];
__device__ float g_att[NP * NH];
__device__ float g_dir[NP * 3];
__device__ float g_xmix[NP * NC];           // 143 MB
__device__ int   g_counts[NN];
__device__ int   g_cursor[NN];
__device__ int   g_offsets[NN + 1];
__device__ int   g_order[NP];

// ---------------- constant memory for edge-model weights ------
__constant__ float c_wmlp[64 * NRBF];
__constant__ float c_bmlp[NRBF];
__constant__ float c_we1[115 * FD];
__constant__ float c_be1[FD];
__constant__ float c_we2[FD * FD];
__constant__ float c_be2[FD];
__constant__ float c_watt[FD * NH];
__constant__ float c_batt[NH];

__device__ __forceinline__ float siluf(float z) { return z / (1.0f + __expf(-z)); }

// tf32 helpers
__device__ __forceinline__ unsigned cvt_tf32(float f) {
    unsigned r; asm("cvt.rna.tf32.f32 %0, %1;" : "=r"(r) : "f"(f)); return r;
}
__device__ __forceinline__ void split_tf32(float f, unsigned& hi, unsigned& lo) {
    asm("cvt.rna.tf32.f32 %0, %1;" : "=r"(hi) : "f"(f));
    float rem = f - __uint_as_float(hi);
    asm("cvt.rna.tf32.f32 %0, %1;" : "=r"(lo) : "f"(rem));
}
__device__ __forceinline__ void mma_tf32(float c[4], const unsigned a[4], const unsigned b[2]) {
    asm("mma.sync.aligned.m16n8k8.row.col.f32.tf32.tf32.f32 "
        "{%0,%1,%2,%3}, {%4,%5,%6,%7}, {%8,%9}, {%0,%1,%2,%3};"
        : "+f"(c[0]), "+f"(c[1]), "+f"(c[2]), "+f"(c[3])
        : "r"(a[0]), "r"(a[1]), "r"(a[2]), "r"(a[3]), "r"(b[0]), "r"(b[1]));
}

// ---------------- CSR build ----------------
__global__ void zero_kernel() {
    int i = blockIdx.x * 256 + threadIdx.x;
    if (i < NN) { g_counts[i] = 0; g_cursor[i] = 0; }
}

__global__ void count_kernel(const int* __restrict__ pl) {
    int p = blockIdx.x * 256 + threadIdx.x;
    if (p < NP) atomicAdd(&g_counts[pl[p]], 1);
}

__global__ void scan_kernel() {
    __shared__ int sh[1024];
    int t = threadIdx.x;
    int carry = 0;
    if (t == 0) g_offsets[0] = 0;
    for (int base = 0; base < NN; base += 1024) {
        int idx = base + t;
        int val = (idx < NN) ? g_counts[idx] : 0;
        sh[t] = val;
        __syncthreads();
        for (int off = 1; off < 1024; off <<= 1) {
            int add = (t >= off) ? sh[t - off] : 0;
            __syncthreads();
            sh[t] += add;
            __syncthreads();
        }
        if (idx < NN) g_offsets[idx + 1] = carry + sh[t];
        int tot = sh[1023];
        __syncthreads();
        carry += tot;
    }
}

__global__ void scatter_kernel(const int* __restrict__ pl) {
    int p = blockIdx.x * 256 + threadIdx.x;
    if (p < NP) {
        int i = pl[p];
        int pos = g_offsets[i] + atomicAdd(&g_cursor[i], 1);
        g_order[pos] = p;
    }
}

// ---------------- edge model (R1 version) ----------------
__global__ void __launch_bounds__(128) edge_kernel(
    const float* __restrict__ h, const float* __restrict__ x,
    const int* __restrict__ pl)
{
    extern __shared__ float smem[];
    float* my = smem + threadIdx.x * 121;
    int p = blockIdx.x * 128 + threadIdx.x;

    int i = pl[p], j = pl[NP + p];
    float xi0 = x[i*3], xi1 = x[i*3+1], xi2 = x[i*3+2];
    float r0 = x[j*3] - xi0, r1 = x[j*3+1] - xi1, r2 = x[j*3+2] - xi2;
    float d = sqrtf(r0*r0 + r1*r1 + r2*r2);
    float inv = 1.0f / (d + 1e-5f);
    g_dir[p*3]   = r0 * inv;
    g_dir[p*3+1] = r1 * inv;
    g_dir[p*3+2] = r2 * inv;

    const float4* hi = (const float4*)(h + i * FD);
    const float4* hj = (const float4*)(h + j * FD);
    #pragma unroll
    for (int q = 0; q < 8; q++) {
        float4 a = hi[q];
        my[4*q] = a.x; my[4*q+1] = a.y; my[4*q+2] = a.z; my[4*q+3] = a.w;
    }
    #pragma unroll
    for (int q = 0; q < 8; q++) {
        float4 a = hj[q];
        my[32+4*q] = a.x; my[32+4*q+1] = a.y; my[32+4*q+2] = a.z; my[32+4*q+3] = a.w;
    }

    float acc[NRBF];
    #pragma unroll
    for (int k = 0; k < NRBF; k++) acc[k] = c_bmlp[k];
    #pragma unroll 2
    for (int c = 0; c < 64; c++) {
        float v = my[c];
        #pragma unroll
        for (int k = 0; k < NRBF; k++) acc[k] += v * c_wmlp[c * NRBF + k];
    }
    #pragma unroll
    for (int k = 0; k < NRBF; k++) {
        float ce = d - (float)k * (5.0f / 49.0f);
        my[64 + k] = __expf(-10.0f * ce * ce) * acc[k];
    }
    my[114] = d;

    float a2[FD];
    #pragma unroll
    for (int k = 0; k < FD; k++) a2[k] = c_be1[k];
    #pragma unroll 2
    for (int c = 0; c < 115; c++) {
        float v = my[c];
        #pragma unroll
        for (int k = 0; k < FD; k++) a2[k] += v * c_we1[c * FD + k];
    }
    #pragma unroll
    for (int k = 0; k < FD; k++) my[k] = siluf(a2[k]);

    float a3[FD];
    #pragma unroll
    for (int k = 0; k < FD; k++) a3[k] = c_be2[k];
    #pragma unroll 2
    for (int c = 0; c < FD; c++) {
        float v = my[c];
        #pragma unroll
        for (int k = 0; k < FD; k++) a3[k] += v * c_we2[c * FD + k];
    }
    #pragma unroll
    for (int k = 0; k < FD; k++) {
        g_hedge[k * NP + p] = a3[k];
        my[k] = a3[k];
    }

    float a4[NH];
    #pragma unroll
    for (int k = 0; k < NH; k++) a4[k] = c_batt[k];
    #pragma unroll 2
    for (int c = 0; c < FD; c++) {
        float v = my[c];
        #pragma unroll
        for (int k = 0; k < NH; k++) a4[k] += v * c_watt[c * NH + k];
    }
    #pragma unroll
    for (int k = 0; k < NH; k++) {
        float z = a4[k];
        float cel = (z > 0.0f) ? z : 2.0f * (__expf(0.5f * z) - 1.0f);
        g_logits[p * NH + k] = cel;
    }
}

// ---------------- scatter softmax ----------------
__global__ void __launch_bounds__(256) softmax_kernel() {
    int node = blockIdx.x * 8 + (threadIdx.x >> 5);
    int lane = threadIdx.x & 31;
    int s = g_offsets[node], e = g_offsets[node + 1];

    float mx[NH];
    #pragma unroll
    for (int k = 0; k < NH; k++) mx[k] = -1e30f;
    for (int idx = s + lane; idx < e; idx += 32) {
        int p = g_order[idx];
        #pragma unroll
        for (int k = 0; k < NH; k++) mx[k] = fmaxf(mx[k], g_logits[p * NH + k]);
    }
    #pragma unroll
    for (int k = 0; k < NH; k++)
        #pragma unroll
        for (int off = 16; off; off >>= 1)
            mx[k] = fmaxf(mx[k], __shfl_xor_sync(0xffffffffu, mx[k], off));

    float sm[NH];
    #pragma unroll
    for (int k = 0; k < NH; k++) sm[k] = 0.0f;
    for (int idx = s + lane; idx < e; idx += 32) {
        int p = g_order[idx];
        #pragma unroll
        for (int k = 0; k < NH; k++) sm[k] += __expf(g_logits[p * NH + k] - mx[k]);
    }
    #pragma unroll
    for (int k = 0; k < NH; k++)
        #pragma unroll
        for (int off = 16; off; off >>= 1)
            sm[k] += __shfl_xor_sync(0xffffffffu, sm[k], off);

    for (int idx = s + lane; idx < e; idx += 32) {
        int p = g_order[idx];
        #pragma unroll
        for (int k = 0; k < NH; k++)
            g_att[p * NH + k] = __expf(g_logits[p * NH + k] - mx[k]) / sm[k];
    }
}

// ---------------- big GEMM via 3xTF32 mma.sync ----------------
// x_mixed = tanh(sem @ w_xmix), sem [64x224] per block, full fp32 accuracy.
// 8 warps: 2 along M (32 rows each) x 4 along N (56 cols each).
// K staged in 4 chunks of 56; smem rows padded to 228 floats (conflict-free).
#define SEMS 228
__global__ void __launch_bounds__(256, 2) gemm_kernel(const float* __restrict__ wx) {
    extern __shared__ float sm[];
    float* sem = sm;               // [64][228] row-major
    float* wt  = sm + 64 * SEMS;   // [56][228]

    int tid = threadIdx.x;
    int m0 = blockIdx.x * 64;

    // stage h_edge [32][64] + att [448] into wt region
    float* s_he = wt;              // 2048 floats
    float* s_att = wt + 2048;      // 448 floats
    {
        int m = tid & 63, f0 = tid >> 6;
        #pragma unroll
        for (int it = 0; it < 8; it++) {
            int f = f0 + 4 * it;
            s_he[f * 64 + m] = g_hedge[f * NP + m0 + m];
        }
    }
    for (int t = tid; t < 448; t += 256) s_att[t] = g_att[m0 * NH + t];
    __syncthreads();

    // sem[m][k] = he[k/7][m] * att[m][k%7]
    for (int idx = tid; idx < 64 * NC; idx += 256) {
        int m = idx / NC, k = idx - m * NC;
        sem[m * SEMS + k] = s_he[(k / 7) * 64 + m] * s_att[m * 7 + (k % 7)];
    }

    int lane = tid & 31, wid = tid >> 5;
    int wm = wid & 1;              // 0..1 : M offset 32*wm
    int wn = wid >> 1;             // 0..3 : N offset 56*wn
    int grp = lane >> 2, tg = lane & 3;

    float C[2][7][4];
    #pragma unroll
    for (int mt = 0; mt < 2; mt++)
        #pragma unroll
        for (int nt = 0; nt < 7; nt++)
            #pragma unroll
            for (int q = 0; q < 4; q++) C[mt][nt][q] = 0.0f;

    for (int kt = 0; kt < 4; kt++) {
        __syncthreads();    // done with wt (staging or previous tile)
        // load W rows [kt*56, kt*56+56) into wt (padded stride 228)
        for (int t4 = tid; t4 < 56 * 56; t4 += 256) {
            int r = t4 / 56, c4 = t4 - r * 56;
            float4 w = *(const float4*)(wx + (kt * 56 + r) * NC + c4 * 4);
            *(float4*)(wt + r * SEMS + c4 * 4) = w;
        }
        __syncthreads();

        #pragma unroll
        for (int k8 = 0; k8 < 7; k8++) {
            int kg = kt * 56 + k8 * 8;   // sem column base
            int kl = k8 * 8;             // wt row base

            // A fragments (2 m16 tiles), split hi/lo
            unsigned Ah[2][4], Al[2][4];
            #pragma unroll
            for (int mt = 0; mt < 2; mt++) {
                int r0 = wm * 32 + mt * 16 + grp;
                float a0 = sem[r0 * SEMS + kg + tg];
                float a1 = sem[(r0 + 8) * SEMS + kg + tg];
                float a2 = sem[r0 * SEMS + kg + tg + 4];
                float a3 = sem[(r0 + 8) * SEMS + kg + tg + 4];
                split_tf32(a0, Ah[mt][0], Al[mt][0]);
                split_tf32(a1, Ah[mt][1], Al[mt][1]);
                split_tf32(a2, Ah[mt][2], Al[mt][2]);
                split_tf32(a3, Ah[mt][3], Al[mt][3]);
            }

            #pragma unroll
            for (int nt = 0; nt < 7; nt++) {
                int n0 = wn * 56 + nt * 8;
                float b0 = wt[(kl + tg) * SEMS + n0 + grp];
                float b1 = wt[(kl + tg + 4) * SEMS + n0 + grp];
                unsigned Bh[2], Bl[2];
                split_tf32(b0, Bh[0], Bl[0]);
                split_tf32(b1, Bh[1], Bl[1]);
                #pragma unroll
                for (int mt = 0; mt < 2; mt++) {
                    mma_tf32(C[mt][nt], Ah[mt], Bh);   // hi*hi
                    mma_tf32(C[mt][nt], Ah[mt], Bl);   // hi*lo
                    mma_tf32(C[mt][nt], Al[mt], Bh);   // lo*hi
                }
            }
        }
    }

    // epilogue: tanh + store
    #pragma unroll
    for (int mt = 0; mt < 2; mt++) {
        int rbase = m0 + wm * 32 + mt * 16 + grp;
        #pragma unroll
        for (int nt = 0; nt < 7; nt++) {
            int n0 = wn * 56 + nt * 8 + 2 * tg;
            float2 lo2 = make_float2(tanhf(C[mt][nt][0]), tanhf(C[mt][nt][1]));
            float2 hi2 = make_float2(tanhf(C[mt][nt][2]), tanhf(C[mt][nt][3]));
            *(float2*)(g_xmix + rbase * NC + n0) = lo2;
            *(float2*)(g_xmix + (rbase + 8) * NC + n0) = hi2;
        }
    }
}

// ---------------- per-node aggregation + node/velocity MLPs (R1 version) ----
__global__ void __launch_bounds__(256) node_kernel(
    const float* __restrict__ h, const float* __restrict__ x, const float* __restrict__ v,
    const float* __restrict__ w_p1, const float* __restrict__ b_p1,
    const float* __restrict__ w_p2, const float* __restrict__ b_p2,
    const float* __restrict__ w_n1, const float* __restrict__ b_n1,
    const float* __restrict__ w_n2, const float* __restrict__ b_n2,
    const float* __restrict__ w_v1, const float* __restrict__ b_v1,
    const float* __restrict__ w_v2, const float* __restrict__ w_vmix,
    float* __restrict__ out)
{
    __shared__ float sh[8 * 512];
    int wid = threadIdx.x >> 5, lane = threadIdx.x & 31;
    float* ws = sh + wid * 512;
    int node = blockIdx.x * 8 + wid;
    int s = g_offsets[node], e = g_offsets[node + 1];

    int fj[7], hj[7];
    #pragma unroll
    for (int j = 0; j < 7; j++) { int c = lane + 32 * j; fj[j] = c / 7; hj[j] = c % 7; }

    float hs[7]  = {0,0,0,0,0,0,0};
    float cb0[7] = {0,0,0,0,0,0,0};
    float cb1[7] = {0,0,0,0,0,0,0};
    float cb2[7] = {0,0,0,0,0,0,0};

    for (int idx = s; idx < e; idx++) {
        int p = g_order[idx];
        ws[448 + lane] = g_hedge[lane * NP + p];
        if (lane < 7) ws[480 + lane] = g_att[p * NH + lane];
        float d0 = g_dir[p*3], d1 = g_dir[p*3+1], d2 = g_dir[p*3+2];
        __syncwarp();
        #pragma unroll
        for (int j = 0; j < 7; j++) {
            int c = lane + 32 * j;
            float xm = g_xmix[p * NC + c];
            hs[j]  += ws[448 + fj[j]] * ws[480 + hj[j]];
            cb0[j] += d0 * xm; cb1[j] += d1 * xm; cb2[j] += d2 * xm;
        }
        __syncwarp();
    }

    float rden = 1.0f / fmaxf((float)(e - s), 1.0f);
    float vp0 = 0, vp1 = 0, vp2 = 0;
    #pragma unroll
    for (int j = 0; j < 7; j++) {
        int c = lane + 32 * j;
        float m0 = cb0[j] * rden, m1 = cb1[j] * rden, m2 = cb2[j] * rden;
        ws[c] = m0*m0 + m1*m1 + m2*m2;
        ws[224 + c] = hs[j];
        float wv = __ldg(&w_vmix[c]);
        vp0 += wv * m0; vp1 += wv * m1; vp2 += wv * m2;
    }
    #pragma unroll
    for (int off = 16; off; off >>= 1) {
        vp0 += __shfl_xor_sync(0xffffffffu, vp0, off);
        vp1 += __shfl_xor_sync(0xffffffffu, vp1, off);
        vp2 += __shfl_xor_sync(0xffffffffu, vp2, off);
    }
    __syncwarp();

    float o1 = __ldg(&b_p1[lane]);
    for (int c = 0; c < NC; c++) o1 += ws[c] * __ldg(&w_p1[c * 32 + lane]);
    o1 = siluf(o1);
    float o2 = __ldg(&b_p2[lane]);
    for (int c = 0; c < 32; c++)
        o2 += __shfl_sync(0xffffffffu, o1, c) * __ldg(&w_p2[c * 32 + lane]);
    float hspat = siluf(o2);

    float hv = h[node * 32 + lane];
    float n1 = __ldg(&b_n1[lane]);
    for (int c = 0; c < 32; c++)
        n1 += __shfl_sync(0xffffffffu, hv, c) * __ldg(&w_n1[c * 32 + lane]);
    for (int c = 0; c < NC; c++)
        n1 += ws[224 + c] * __ldg(&w_n1[(32 + c) * 32 + lane]);
    for (int c = 0; c < 32; c++)
        n1 += __shfl_sync(0xffffffffu, hspat, c) * __ldg(&w_n1[(256 + c) * 32 + lane]);
    n1 = siluf(n1);
    float n2 = __ldg(&b_n2[lane]);
    for (int c = 0; c < 32; c++)
        n2 += __shfl_sync(0xffffffffu, n1, c) * __ldg(&w_n2[c * 32 + lane]);
    float hup = hv + siluf(n2);
    out[node * 32 + lane] = hup;

    float v1 = __ldg(&b_v1[lane]);
    for (int c = 0; c < 32; c++)
        v1 += __shfl_sync(0xffffffffu, hv, c) * __ldg(&w_v1[c * 32 + lane]);
    v1 = siluf(v1);
    float sv = v1 * __ldg(&w_v2[lane]);
    #pragma unroll
    for (int off = 16; off; off >>= 1) sv += __shfl_xor_sync(0xffffffffu, sv, off);
    float scale = 2.0f / (1.0f + __expf(-sv));

    if (lane < 3) {
        float dv = (lane == 0) ? vp0 : ((lane == 1) ? vp1 : vp2);
        float vu = scale * v[node * 3 + lane] + dv;
        out[NN * 32 + node * 3 + lane] = x[node * 3 + lane] + vu;
        out[NN * 32 + NN * 3 + node * 3 + lane] = vu;
    }
}

// ---------------- launch ----------------
extern "C" void kernel_launch(void* const* d_in, const int* in_sizes, int n_in,
                              void* d_out, int out_size)
{
    const float* h  = (const float*)d_in[0];
    const float* x  = (const float*)d_in[1];
    const float* v  = (const float*)d_in[2];
    const int*   pl = (const int*)d_in[3];

    cudaMemcpyToSymbolAsync(c_wmlp, d_in[4], 64 * NRBF * 4, 0, cudaMemcpyDeviceToDevice, 0);
    cudaMemcpyToSymbolAsync(c_bmlp, d_in[5], NRBF * 4,      0, cudaMemcpyDeviceToDevice, 0);
    cudaMemcpyToSymbolAsync(c_we1,  d_in[6], 115 * FD * 4,  0, cudaMemcpyDeviceToDevice, 0);
    cudaMemcpyToSymbolAsync(c_be1,  d_in[7], FD * 4,        0, cudaMemcpyDeviceToDevice, 0);
    cudaMemcpyToSymbolAsync(c_we2,  d_in[8], FD * FD * 4,   0, cudaMemcpyDeviceToDevice, 0);
    cudaMemcpyToSymbolAsync(c_be2,  d_in[9], FD * 4,        0, cudaMemcpyDeviceToDevice, 0);
    cudaMemcpyToSymbolAsync(c_watt, d_in[10], FD * NH * 4,  0, cudaMemcpyDeviceToDevice, 0);
    cudaMemcpyToSymbolAsync(c_batt, d_in[11], NH * 4,       0, cudaMemcpyDeviceToDevice, 0);

    int edge_smem = 128 * 121 * 4;
    int gemm_smem = (64 * SEMS + 56 * SEMS) * 4;   // 109,440 B
    cudaFuncSetAttribute(edge_kernel, cudaFuncAttributeMaxDynamicSharedMemorySize, edge_smem);
    cudaFuncSetAttribute(gemm_kernel, cudaFuncAttributeMaxDynamicSharedMemorySize, gemm_smem);

    zero_kernel<<<(NN + 255) / 256, 256>>>();
    count_kernel<<<(NP + 255) / 256, 256>>>(pl);
    scan_kernel<<<1, 1024>>>();
    scatter_kernel<<<(NP + 255) / 256, 256>>>(pl);

    edge_kernel<<<NP / 128, 128, edge_smem>>>(h, x, pl);
    softmax_kernel<<<NN / 8, 256>>>();
    gemm_kernel<<<NP / 64, 256, gemm_smem>>>((const float*)d_in[23]);

    node_kernel<<<NN / 8, 256>>>(
        h, x, v,
        (const float*)d_in[16], (const float*)d_in[17],   // w_p1, b_p1
        (const float*)d_in[18], (const float*)d_in[19],   // w_p2, b_p2
        (const float*)d_in[12], (const float*)d_in[13],   // w_n1, b_n1
        (const float*)d_in[14], (const float*)d_in[15],   // w_n2, b_n2
        (const float*)d_in[20], (const float*)d_in[21],   // w_v1, b_v1
        (const float*)d_in[22], (const float*)d_in[24],   // w_v2, w_vmix
        (float*)d_out);
}